// round 1
// baseline (speedup 1.0000x reference)
#include <cuda_runtime.h>
#include <math.h>

#define BB 2
#define LL 2048
#define DD 1024
#define HH 16
#define HD 64
#define MM (BB*LL)   // 4096

// Scratch (device globals: no allocation, graph-capture safe)
__device__ float g_q[BB*LL*DD];
__device__ float g_k[BB*LL*DD];
__device__ float g_v[BB*LL*DD];
__device__ float g_att[BB*LL*DD];

// C = A @ W^T + bias.  A: (M x K) row-major, W: (N x K) row-major.
// LAYOUT 0: C row-major (M x N).  LAYOUT 1: C written as (B,H,L,HD) for attention.
template<int LAYOUT>
__global__ __launch_bounds__(256) void gemm_bias(const float* __restrict__ A,
                                                 const float* __restrict__ W,
                                                 const float* __restrict__ bias,
                                                 float* __restrict__ C)
{
    const int K = DD, N = DD;
    __shared__ float As[16][65];
    __shared__ float Ws[16][65];
    int tid = threadIdx.x;
    int ty = tid >> 4, tx = tid & 15;
    int m0 = blockIdx.y * 64, n0 = blockIdx.x * 64;

    float acc[4][4] = {};
    int r  = tid >> 2;          // 0..63
    int c4 = (tid & 3) << 2;    // 0,4,8,12
    const float* Ap = A + (size_t)(m0 + r) * K + c4;
    const float* Wp = W + (size_t)(n0 + r) * K + c4;

    for (int k0 = 0; k0 < K; k0 += 16) {
        float4 av = *(const float4*)(Ap + k0);
        float4 wv = *(const float4*)(Wp + k0);
        __syncthreads();
        As[c4 + 0][r] = av.x; As[c4 + 1][r] = av.y;
        As[c4 + 2][r] = av.z; As[c4 + 3][r] = av.w;
        Ws[c4 + 0][r] = wv.x; Ws[c4 + 1][r] = wv.y;
        Ws[c4 + 2][r] = wv.z; Ws[c4 + 3][r] = wv.w;
        __syncthreads();
#pragma unroll
        for (int kk = 0; kk < 16; kk++) {
            float a[4], b[4];
#pragma unroll
            for (int i = 0; i < 4; i++) a[i] = As[kk][ty * 4 + i];
#pragma unroll
            for (int j = 0; j < 4; j++) b[j] = Ws[kk][tx * 4 + j];
#pragma unroll
            for (int i = 0; i < 4; i++)
#pragma unroll
                for (int j = 0; j < 4; j++)
                    acc[i][j] += a[i] * b[j];
        }
    }

#pragma unroll
    for (int i = 0; i < 4; i++) {
        int m = m0 + ty * 4 + i;
#pragma unroll
        for (int j = 0; j < 4; j++) {
            int n = n0 + tx * 4 + j;
            float val = acc[i][j] + bias[n];
            if (LAYOUT == 0) {
                C[(size_t)m * N + n] = val;
            } else {
                int b_ = m / LL, l_ = m % LL;
                int h_ = n >> 6, hd_ = n & 63;
                C[(((size_t)(b_ * HH + h_)) * LL + l_) * HD + hd_] = val;
            }
        }
    }
}

// Flash attention over (B,H,L,HD) q/k/v.  One CTA = one 64-row Q tile of one (b,h).
// Output written directly in (B, L, D) layout for the final projection GEMM.
__global__ __launch_bounds__(256) void attn_kernel(const float* __restrict__ q,
                                                   const float* __restrict__ k,
                                                   const float* __restrict__ v,
                                                   float* __restrict__ out)
{
    extern __shared__ float sm[];
    float* Qs = sm;              // 64 x 65
    float* Ks = Qs + 64 * 65;    // 64 x 65
    float* Vs = Ks + 64 * 65;    // 64 x 65
    float* Ps = Vs + 64 * 65;    // 64 x 65

    int tid = threadIdx.x;
    int ty = tid >> 4, tx = tid & 15;
    int qt = blockIdx.x, h = blockIdx.y, b = blockIdx.z;
    size_t base = ((size_t)(b * HH + h)) * LL * HD;
    const float* qb = q + base + (size_t)qt * 64 * HD;

    // Load Q tile
    for (int i = tid; i < 64 * 16; i += 256) {
        int rr = i >> 4, cc = (i & 15) << 2;
        float4 v4 = *(const float4*)(qb + rr * HD + cc);
        Qs[rr * 65 + cc]     = v4.x;
        Qs[rr * 65 + cc + 1] = v4.y;
        Qs[rr * 65 + cc + 2] = v4.z;
        Qs[rr * 65 + cc + 3] = v4.w;
    }

    float m_i[4], l_i[4], O[4][4];
#pragma unroll
    for (int i = 0; i < 4; i++) {
        m_i[i] = -1e30f; l_i[i] = 0.f;
#pragma unroll
        for (int j = 0; j < 4; j++) O[i][j] = 0.f;
    }
    const float scale = 0.125f;  // 1/sqrt(64)

    for (int kt = 0; kt < LL / 64; kt++) {
        const float* kb = k + base + (size_t)kt * 64 * HD;
        const float* vb = v + base + (size_t)kt * 64 * HD;
        __syncthreads();   // previous PV done before overwriting Ks/Vs
        for (int i = tid; i < 64 * 16; i += 256) {
            int rr = i >> 4, cc = (i & 15) << 2;
            float4 kv = *(const float4*)(kb + rr * HD + cc);
            Ks[rr * 65 + cc]     = kv.x;
            Ks[rr * 65 + cc + 1] = kv.y;
            Ks[rr * 65 + cc + 2] = kv.z;
            Ks[rr * 65 + cc + 3] = kv.w;
            float4 vv = *(const float4*)(vb + rr * HD + cc);
            Vs[rr * 65 + cc]     = vv.x;
            Vs[rr * 65 + cc + 1] = vv.y;
            Vs[rr * 65 + cc + 2] = vv.z;
            Vs[rr * 65 + cc + 3] = vv.w;
        }
        __syncthreads();

        // S = scale * Q K^T   (each thread 4x4 of the 64x64 tile)
        float s[4][4];
#pragma unroll
        for (int i = 0; i < 4; i++)
#pragma unroll
            for (int j = 0; j < 4; j++) s[i][j] = 0.f;
#pragma unroll
        for (int d = 0; d < 64; d++) {
            float a[4], bb[4];
#pragma unroll
            for (int i = 0; i < 4; i++) a[i]  = Qs[(ty * 4 + i) * 65 + d];
#pragma unroll
            for (int j = 0; j < 4; j++) bb[j] = Ks[(tx * 4 + j) * 65 + d];
#pragma unroll
            for (int i = 0; i < 4; i++)
#pragma unroll
                for (int j = 0; j < 4; j++)
                    s[i][j] += a[i] * bb[j];
        }

        // Online softmax update (row stats shared across the 16 lanes with same ty)
#pragma unroll
        for (int i = 0; i < 4; i++) {
#pragma unroll
            for (int j = 0; j < 4; j++) s[i][j] *= scale;
            float tm = fmaxf(fmaxf(s[i][0], s[i][1]), fmaxf(s[i][2], s[i][3]));
#pragma unroll
            for (int o = 1; o < 16; o <<= 1)
                tm = fmaxf(tm, __shfl_xor_sync(0xffffffffu, tm, o));
            float mn = fmaxf(m_i[i], tm);
            float alpha = __expf(m_i[i] - mn);
            m_i[i] = mn;
            float rs = 0.f;
#pragma unroll
            for (int j = 0; j < 4; j++) {
                s[i][j] = __expf(s[i][j] - mn);
                rs += s[i][j];
            }
#pragma unroll
            for (int o = 1; o < 16; o <<= 1)
                rs += __shfl_xor_sync(0xffffffffu, rs, o);
            l_i[i] = l_i[i] * alpha + rs;
#pragma unroll
            for (int j = 0; j < 4; j++) O[i][j] *= alpha;
#pragma unroll
            for (int j = 0; j < 4; j++)
                Ps[(ty * 4 + i) * 65 + tx * 4 + j] = s[i][j];
        }
        __syncthreads();

        // O += P V
#pragma unroll
        for (int kr = 0; kr < 64; kr++) {
            float p[4], vv[4];
#pragma unroll
            for (int i = 0; i < 4; i++) p[i]  = Ps[(ty * 4 + i) * 65 + kr];
#pragma unroll
            for (int j = 0; j < 4; j++) vv[j] = Vs[kr * 65 + tx * 4 + j];
#pragma unroll
            for (int i = 0; i < 4; i++)
#pragma unroll
                for (int j = 0; j < 4; j++)
                    O[i][j] += p[i] * vv[j];
        }
    }

    // Write to (B, L, D): column h*64 + n
    int ql0 = qt * 64;
#pragma unroll
    for (int i = 0; i < 4; i++) {
        int l_ = ql0 + ty * 4 + i;
        float inv = 1.f / l_i[i];
#pragma unroll
        for (int j = 0; j < 4; j++) {
            out[((size_t)b * LL + l_) * DD + h * HD + tx * 4 + j] = O[i][j] * inv;
        }
    }
}

extern "C" void kernel_launch(void* const* d_in, const int* in_sizes, int n_in,
                              void* d_out, int out_size) {
    const float* x  = (const float*)d_in[0];
    const float* Wq = (const float*)d_in[1];
    const float* bq = (const float*)d_in[2];
    const float* Wk = (const float*)d_in[3];
    const float* bk = (const float*)d_in[4];
    const float* Wv = (const float*)d_in[5];
    const float* bv = (const float*)d_in[6];
    const float* Wo = (const float*)d_in[7];
    const float* bo = (const float*)d_in[8];
    float* out = (float*)d_out;

    float *q, *k, *v, *att;
    cudaGetSymbolAddress((void**)&q,   g_q);
    cudaGetSymbolAddress((void**)&k,   g_k);
    cudaGetSymbolAddress((void**)&v,   g_v);
    cudaGetSymbolAddress((void**)&att, g_att);

    dim3 gg(DD / 64, MM / 64);
    gemm_bias<1><<<gg, 256>>>(x, Wq, bq, q);
    gemm_bias<1><<<gg, 256>>>(x, Wk, bk, k);
    gemm_bias<1><<<gg, 256>>>(x, Wv, bv, v);

    const int smem = 4 * 64 * 65 * (int)sizeof(float);  // 66560 B
    cudaFuncSetAttribute(attn_kernel, cudaFuncAttributeMaxDynamicSharedMemorySize, smem);
    attn_kernel<<<dim3(LL / 64, HH, BB), 256, smem>>>(q, k, v, att);

    gemm_bias<0><<<gg, 256>>>(att, Wo, bo, out);
}

// round 2
// speedup vs baseline: 1.5612x; 1.5612x over previous
#include <cuda_runtime.h>
#include <math.h>
#include <stdint.h>

#define BB 2
#define LL 2048
#define DD 1024
#define HH 16
#define HD 64
#define MM (BB*LL)   // 4096

// Scratch (device globals: no allocation, graph-capture safe)
__device__ float g_q[BB*LL*DD];
__device__ float g_k[BB*LL*DD];
__device__ float g_v[BB*LL*DD];
__device__ float g_att[BB*LL*DD];

__device__ __forceinline__ uint32_t f2tf(float x) {
    uint32_t r; asm("cvt.rna.tf32.f32 %0, %1;" : "=r"(r) : "f"(x)); return r;
}

__device__ __forceinline__ void mma8(float* d, const uint32_t* a, const uint32_t* b) {
    asm volatile("mma.sync.aligned.m16n8k8.row.col.f32.tf32.tf32.f32 "
                 "{%0,%1,%2,%3}, {%4,%5,%6,%7}, {%8,%9}, {%0,%1,%2,%3};"
                 : "+f"(d[0]), "+f"(d[1]), "+f"(d[2]), "+f"(d[3])
                 : "r"(a[0]), "r"(a[1]), "r"(a[2]), "r"(a[3]),
                   "r"(b[0]), "r"(b[1]));
}

// ---------------------------------------------------------------------------
// C = A @ W^T + bias, M=4096, N=K=1024.  A:(M,K) row-major, W:(N,K) row-major.
// LAYOUT 0: C row-major (M,N).  LAYOUT 1: C as (B,H,L,HD).  CVT_OUT: round
// result to tf32 so downstream kernels can copy without converting.
// CTA tile 128x128x32; 8 warps (4 in m x 2 in n), warp tile 32x64.
// ---------------------------------------------------------------------------
#define GBM 128
#define GBN 128
#define GBK 32
#define GSTR 36   // 36 % 32 == 4 -> conflict-free fragment loads

template<int LAYOUT, int CVT_OUT>
__global__ __launch_bounds__(256) void gemm_tc(const float* __restrict__ A,
                                               const float* __restrict__ W,
                                               const float* __restrict__ bias,
                                               float* __restrict__ C)
{
    __shared__ uint32_t As[GBM * GSTR];
    __shared__ uint32_t Ws[GBN * GSTR];

    const int tid = threadIdx.x;
    const int warp = tid >> 5, lane = tid & 31;
    const int wm = warp & 3, wn = warp >> 2;       // 4 x 2 warps
    const int m0 = blockIdx.y * GBM, n0 = blockIdx.x * GBN;

    float acc[2][8][4];
#pragma unroll
    for (int mf = 0; mf < 2; mf++)
#pragma unroll
        for (int nf = 0; nf < 8; nf++)
#pragma unroll
            for (int j = 0; j < 4; j++) acc[mf][nf][j] = 0.f;

    const int lr = tid >> 1;             // 0..127
    const int lc = (tid & 1) * 16;       // 0 or 16
    const float* Ap = A + (size_t)(m0 + lr) * DD + lc;
    const float* Wp = W + (size_t)(n0 + lr) * DD + lc;

    for (int k0 = 0; k0 < DD; k0 += GBK) {
        float4 av[4], wv[4];
#pragma unroll
        for (int i = 0; i < 4; i++) {
            av[i] = *(const float4*)(Ap + k0 + i * 4);
            wv[i] = *(const float4*)(Wp + k0 + i * 4);
        }
        __syncthreads();
#pragma unroll
        for (int i = 0; i < 4; i++) {
            uint4 ua = make_uint4(f2tf(av[i].x), f2tf(av[i].y), f2tf(av[i].z), f2tf(av[i].w));
            uint4 uw = make_uint4(f2tf(wv[i].x), f2tf(wv[i].y), f2tf(wv[i].z), f2tf(wv[i].w));
            *(uint4*)&As[lr * GSTR + lc + i * 4] = ua;
            *(uint4*)&Ws[lr * GSTR + lc + i * 4] = uw;
        }
        __syncthreads();

#pragma unroll
        for (int ks = 0; ks < 4; ks++) {
            const int c = ks * 8 + (lane & 3);
            uint32_t a[2][4], b[8][2];
#pragma unroll
            for (int mf = 0; mf < 2; mf++) {
                const int rb = wm * 32 + mf * 16 + (lane >> 2);
                a[mf][0] = As[rb * GSTR + c];
                a[mf][1] = As[(rb + 8) * GSTR + c];
                a[mf][2] = As[rb * GSTR + c + 4];
                a[mf][3] = As[(rb + 8) * GSTR + c + 4];
            }
#pragma unroll
            for (int nf = 0; nf < 8; nf++) {
                const int nb = wn * 64 + nf * 8 + (lane >> 2);
                b[nf][0] = Ws[nb * GSTR + c];
                b[nf][1] = Ws[nb * GSTR + c + 4];
            }
#pragma unroll
            for (int mf = 0; mf < 2; mf++)
#pragma unroll
                for (int nf = 0; nf < 8; nf++)
                    mma8(acc[mf][nf], a[mf], b[nf]);
        }
    }

    // epilogue
#pragma unroll
    for (int mf = 0; mf < 2; mf++) {
        const int mbase = m0 + wm * 32 + mf * 16 + (lane >> 2);
#pragma unroll
        for (int nf = 0; nf < 8; nf++) {
            const int nbase = n0 + wn * 64 + nf * 8 + (lane & 3) * 2;
#pragma unroll
            for (int jj = 0; jj < 4; jj++) {
                const int m = mbase + ((jj >= 2) ? 8 : 0);
                const int n = nbase + (jj & 1);
                float val = acc[mf][nf][jj] + bias[n];
                if (CVT_OUT) val = __uint_as_float(f2tf(val));
                if (LAYOUT == 0) {
                    C[(size_t)m * DD + n] = val;
                } else {
                    const int b_ = m >> 11, l_ = m & 2047;
                    const int h_ = n >> 6, hd_ = n & 63;
                    C[(((size_t)(b_ * HH + h_)) * LL + l_) * HD + hd_] = val;
                }
            }
        }
    }
}

// ---------------------------------------------------------------------------
// Flash attention on tensor cores. One CTA = 64 Q rows of one (b,h).
// 128 threads (4 warps), warp owns 16 Q rows. Inputs already tf32-rounded.
// ---------------------------------------------------------------------------
#define QSTR 68   // 68 % 32 == 4
#define VSTR 72   // 72 % 32 == 8

__global__ __launch_bounds__(128) void attn_tc(const float* __restrict__ q,
                                               const float* __restrict__ k,
                                               const float* __restrict__ v,
                                               float* __restrict__ out)
{
    extern __shared__ uint32_t sm[];
    uint32_t* Qs = sm;                  // 64 x QSTR
    uint32_t* Ks = Qs + 64 * QSTR;      // 64 x QSTR
    uint32_t* Vs = Ks + 64 * QSTR;      // 64 x VSTR
    uint32_t* Ps = Vs + 64 * VSTR;      // 64 x QSTR

    const int tid = threadIdx.x, warp = tid >> 5, lane = tid & 31;
    const int qt = blockIdx.x, h = blockIdx.y, b = blockIdx.z;
    const size_t base = ((size_t)(b * HH + h)) * LL * HD;
    const float* qb = q + base + (size_t)qt * 64 * HD;

    // Load Q tile, folding in softmax scale 1/8 (exact power of two)
    {
        const int rr = tid >> 1, c0 = (tid & 1) * 32;
#pragma unroll
        for (int i = 0; i < 8; i++) {
            float4 v4 = *(const float4*)(qb + rr * HD + c0 + i * 4);
            uint4 u = make_uint4(__float_as_uint(v4.x * 0.125f),
                                 __float_as_uint(v4.y * 0.125f),
                                 __float_as_uint(v4.z * 0.125f),
                                 __float_as_uint(v4.w * 0.125f));
            *(uint4*)&Qs[rr * QSTR + c0 + i * 4] = u;
        }
    }

    const int rA = warp * 16 + (lane >> 2);   // this thread's first row
    float mA = -1e30f, mB = -1e30f, lsumA = 0.f, lsumB = 0.f;
    float O[8][4];
#pragma unroll
    for (int nf = 0; nf < 8; nf++)
#pragma unroll
        for (int j = 0; j < 4; j++) O[nf][j] = 0.f;

    for (int kt = 0; kt < LL / 64; kt++) {
        const float* kb = k + base + (size_t)kt * 64 * HD;
        const float* vb = v + base + (size_t)kt * 64 * HD;
        __syncthreads();   // prev PV (and first-iter Q fill) complete
        {
            const int rr = tid >> 1, c0 = (tid & 1) * 32;
#pragma unroll
            for (int i = 0; i < 8; i++) {
                *(uint4*)&Ks[rr * QSTR + c0 + i * 4] = *(const uint4*)(kb + rr * HD + c0 + i * 4);
                *(uint4*)&Vs[rr * VSTR + c0 + i * 4] = *(const uint4*)(vb + rr * HD + c0 + i * 4);
            }
        }
        __syncthreads();

        // S = (Q*scale) @ K^T   (64x64 per CTA, 16x64 per warp)
        float s[8][4];
#pragma unroll
        for (int nf = 0; nf < 8; nf++)
#pragma unroll
            for (int j = 0; j < 4; j++) s[nf][j] = 0.f;

#pragma unroll
        for (int ks = 0; ks < 8; ks++) {
            const int c = ks * 8 + (lane & 3);
            uint32_t a[4], bf[8][2];
            a[0] = Qs[rA * QSTR + c];
            a[1] = Qs[(rA + 8) * QSTR + c];
            a[2] = Qs[rA * QSTR + c + 4];
            a[3] = Qs[(rA + 8) * QSTR + c + 4];
#pragma unroll
            for (int nf = 0; nf < 8; nf++) {
                const int nb = nf * 8 + (lane >> 2);
                bf[nf][0] = Ks[nb * QSTR + c];
                bf[nf][1] = Ks[nb * QSTR + c + 4];
            }
#pragma unroll
            for (int nf = 0; nf < 8; nf++)
                mma8(s[nf], a, bf[nf]);
        }

        // Online softmax (rows rA and rA+8; quad of lanes shares each row)
        float rmA = -1e30f, rmB = -1e30f;
#pragma unroll
        for (int nf = 0; nf < 8; nf++) {
            rmA = fmaxf(rmA, fmaxf(s[nf][0], s[nf][1]));
            rmB = fmaxf(rmB, fmaxf(s[nf][2], s[nf][3]));
        }
#pragma unroll
        for (int o = 1; o < 4; o <<= 1) {
            rmA = fmaxf(rmA, __shfl_xor_sync(0xffffffffu, rmA, o));
            rmB = fmaxf(rmB, __shfl_xor_sync(0xffffffffu, rmB, o));
        }
        const float mnA = fmaxf(mA, rmA), mnB = fmaxf(mB, rmB);
        const float alphaA = __expf(mA - mnA), alphaB = __expf(mB - mnB);
        mA = mnA; mB = mnB;

        float sumA = 0.f, sumB = 0.f;
#pragma unroll
        for (int nf = 0; nf < 8; nf++) {
            s[nf][0] = __expf(s[nf][0] - mnA);
            s[nf][1] = __expf(s[nf][1] - mnA);
            s[nf][2] = __expf(s[nf][2] - mnB);
            s[nf][3] = __expf(s[nf][3] - mnB);
            sumA += s[nf][0] + s[nf][1];
            sumB += s[nf][2] + s[nf][3];
        }
#pragma unroll
        for (int o = 1; o < 4; o <<= 1) {
            sumA += __shfl_xor_sync(0xffffffffu, sumA, o);
            sumB += __shfl_xor_sync(0xffffffffu, sumB, o);
        }
        lsumA = lsumA * alphaA + sumA;
        lsumB = lsumB * alphaB + sumB;
#pragma unroll
        for (int nf = 0; nf < 8; nf++) {
            O[nf][0] *= alphaA; O[nf][1] *= alphaA;
            O[nf][2] *= alphaB; O[nf][3] *= alphaB;
        }

        // Write P (tf32) — each warp touches only its own 16 rows
#pragma unroll
        for (int nf = 0; nf < 8; nf++) {
            const int col = nf * 8 + (lane & 3) * 2;
            *(uint2*)&Ps[rA * QSTR + col]       = make_uint2(f2tf(s[nf][0]), f2tf(s[nf][1]));
            *(uint2*)&Ps[(rA + 8) * QSTR + col] = make_uint2(f2tf(s[nf][2]), f2tf(s[nf][3]));
        }
        __syncwarp();

        // O += P @ V
#pragma unroll
        for (int ks = 0; ks < 8; ks++) {
            const int kk = ks * 8 + (lane & 3);
            uint32_t a[4], bf[2];
            a[0] = Ps[rA * QSTR + ks * 8 + (lane & 3)];
            a[1] = Ps[(rA + 8) * QSTR + ks * 8 + (lane & 3)];
            a[2] = Ps[rA * QSTR + ks * 8 + (lane & 3) + 4];
            a[3] = Ps[(rA + 8) * QSTR + ks * 8 + (lane & 3) + 4];
#pragma unroll
            for (int nf = 0; nf < 8; nf++) {
                const int nb = nf * 8 + (lane >> 2);
                bf[0] = Vs[kk * VSTR + nb];
                bf[1] = Vs[(kk + 4) * VSTR + nb];
                mma8(O[nf], a, bf);
            }
        }
    }

    // Output to (B, L, D) for the final projection
    const float invA = 1.f / lsumA, invB = 1.f / lsumB;
    const int lA = qt * 64 + rA;
#pragma unroll
    for (int nf = 0; nf < 8; nf++) {
        const int d0 = h * HD + nf * 8 + (lane & 3) * 2;
        float* oA = out + ((size_t)b * LL + lA) * DD + d0;
        float* oB = out + ((size_t)b * LL + lA + 8) * DD + d0;
        oA[0] = O[nf][0] * invA; oA[1] = O[nf][1] * invA;
        oB[0] = O[nf][2] * invB; oB[1] = O[nf][3] * invB;
    }
}

extern "C" void kernel_launch(void* const* d_in, const int* in_sizes, int n_in,
                              void* d_out, int out_size) {
    const float* x  = (const float*)d_in[0];
    const float* Wq = (const float*)d_in[1];
    const float* bq = (const float*)d_in[2];
    const float* Wk = (const float*)d_in[3];
    const float* bk = (const float*)d_in[4];
    const float* Wv = (const float*)d_in[5];
    const float* bv = (const float*)d_in[6];
    const float* Wo = (const float*)d_in[7];
    const float* bo = (const float*)d_in[8];
    float* out = (float*)d_out;

    float *q, *k, *v, *att;
    cudaGetSymbolAddress((void**)&q,   g_q);
    cudaGetSymbolAddress((void**)&k,   g_k);
    cudaGetSymbolAddress((void**)&v,   g_v);
    cudaGetSymbolAddress((void**)&att, g_att);

    dim3 gg(DD / GBN, MM / GBM);
    gemm_tc<1, 1><<<gg, 256>>>(x, Wq, bq, q);
    gemm_tc<1, 1><<<gg, 256>>>(x, Wk, bk, k);
    gemm_tc<1, 1><<<gg, 256>>>(x, Wv, bv, v);

    const int smem = (3 * 64 * QSTR + 64 * VSTR) * (int)sizeof(uint32_t);  // ~70.7 KB
    cudaFuncSetAttribute(attn_tc, cudaFuncAttributeMaxDynamicSharedMemorySize, smem);
    attn_tc<<<dim3(LL / 64, HH, BB), 128, smem>>>(q, k, v, att);

    gemm_tc<0, 0><<<gg, 256>>>(att, Wo, bo, out);
}

// round 3
// speedup vs baseline: 8.8736x; 5.6838x over previous
#include <cuda_runtime.h>
#include <cuda_fp16.h>
#include <stdint.h>

#define BB 2
#define LL 2048
#define DD 1024
#define HH 16
#define HD 64
#define MM (BB*LL)   // 4096

// fp16 scratch (device globals: no allocation, graph-capture safe)
__device__ __align__(128) __half g_xh[MM * DD];
__device__ __align__(128) __half g_wh[4][DD * DD];
__device__ __align__(128) __half g_qh[BB * LL * DD];
__device__ __align__(128) __half g_kh[BB * LL * DD];
__device__ __align__(128) __half g_vh[BB * LL * DD];
__device__ __align__(128) __half g_ah[BB * LL * DD];

// ---------------------------------------------------------------- helpers
__device__ __forceinline__ uint32_t smem_u32(const void* p) {
    return (uint32_t)__cvta_generic_to_shared(p);
}
__device__ __forceinline__ void cpasync16(uint32_t s, const void* g) {
    asm volatile("cp.async.cg.shared.global [%0], [%1], 16;\n" :: "r"(s), "l"(g));
}
__device__ __forceinline__ void cp_commit() { asm volatile("cp.async.commit_group;\n"); }
__device__ __forceinline__ void cp_wait0() { asm volatile("cp.async.wait_group 0;\n"); }
__device__ __forceinline__ void cp_wait1() { asm volatile("cp.async.wait_group 1;\n"); }

__device__ __forceinline__ void ldsm4(uint32_t& r0, uint32_t& r1, uint32_t& r2, uint32_t& r3, uint32_t a) {
    asm volatile("ldmatrix.sync.aligned.m8n8.x4.shared.b16 {%0,%1,%2,%3}, [%4];\n"
                 : "=r"(r0), "=r"(r1), "=r"(r2), "=r"(r3) : "r"(a));
}
__device__ __forceinline__ void ldsm4t(uint32_t& r0, uint32_t& r1, uint32_t& r2, uint32_t& r3, uint32_t a) {
    asm volatile("ldmatrix.sync.aligned.m8n8.x4.trans.shared.b16 {%0,%1,%2,%3}, [%4];\n"
                 : "=r"(r0), "=r"(r1), "=r"(r2), "=r"(r3) : "r"(a));
}
__device__ __forceinline__ void mma16(float* d, const uint32_t* a, const uint32_t* b) {
    asm volatile("mma.sync.aligned.m16n8k16.row.col.f32.f16.f16.f32 "
                 "{%0,%1,%2,%3}, {%4,%5,%6,%7}, {%8,%9}, {%0,%1,%2,%3};"
                 : "+f"(d[0]), "+f"(d[1]), "+f"(d[2]), "+f"(d[3])
                 : "r"(a[0]), "r"(a[1]), "r"(a[2]), "r"(a[3]), "r"(b[0]), "r"(b[1]));
}
__device__ __forceinline__ uint32_t packh2(float a, float b) {
    __half2 t = __floats2half2_rn(a, b);
    return *reinterpret_cast<uint32_t*>(&t);
}

// ---------------------------------------------------------------- convert
__global__ void to_half(const float* __restrict__ in, __half* __restrict__ out, int n4) {
    int i = blockIdx.x * blockDim.x + threadIdx.x;
    if (i < n4) {
        float4 v = ((const float4*)in)[i];
        __half2* o = (__half2*)out + (size_t)i * 2;
        o[0] = __floats2half2_rn(v.x, v.y);
        o[1] = __floats2half2_rn(v.z, v.w);
    }
}

// ---------------------------------------------------------------- GEMM
// C = A @ W^T + bias.  A:(M,K) fp16 row-major, W:(N,K) fp16 row-major.
// CTA tile 128x128x64(halves), 8 warps (4m x 2n), warp 32x64.
// LAYOUT 0: out row-major. LAYOUT 1: out (B,H,L,HD). SCALE: *0.125 (for q).
// OUTF32: write fp32 to Cf else fp16 to Ch.
template<int LAYOUT, int SCALE, int OUTF32>
__global__ __launch_bounds__(256, 2) void gemm_h(const __half* __restrict__ A,
                                                 const __half* __restrict__ W,
                                                 const float* __restrict__ bias,
                                                 float* __restrict__ Cf,
                                                 __half* __restrict__ Ch)
{
    extern __shared__ __half smh[];
    const uint32_t sbase = smem_u32(smh);
    const int tid = threadIdx.x, lane = tid & 31, warp = tid >> 5;
    const int wm = warp & 3, wn = warp >> 2;
    const int m0 = blockIdx.y * 128, n0 = blockIdx.x * 128;
    const int g = lane >> 3, lr = lane & 7;

    float acc[2][8][4];
#pragma unroll
    for (int mf = 0; mf < 2; mf++)
#pragma unroll
        for (int nf = 0; nf < 8; nf++)
#pragma unroll
            for (int j = 0; j < 4; j++) acc[mf][nf][j] = 0.f;

    // A buffers at byte 0 / 16384, W buffers at 32768 / 49152
    auto issue = [&](int buf, int k0) {
#pragma unroll
        for (int i = 0; i < 4; i++) {
            int lin = tid + i * 256;
            int row = lin >> 3, cc = lin & 7;
            uint32_t soff = (uint32_t)(row * 128 + ((cc ^ (row & 7)) << 4));
            cpasync16(sbase + buf * 16384 + soff, A + (size_t)(m0 + row) * DD + k0 + cc * 8);
            cpasync16(sbase + 32768 + buf * 16384 + soff, W + (size_t)(n0 + row) * DD + k0 + cc * 8);
        }
    };

    issue(0, 0); cp_commit();

    for (int kt = 0; kt < 16; kt++) {
        if (kt < 15) { issue((kt + 1) & 1, (kt + 1) * 64); cp_commit(); cp_wait1(); }
        else cp_wait0();
        __syncthreads();

        const uint32_t abase = sbase + (kt & 1) * 16384;
        const uint32_t wbase = sbase + 32768 + (kt & 1) * 16384;
#pragma unroll
        for (int ks = 0; ks < 4; ks++) {
            uint32_t a[2][4];
#pragma unroll
            for (int mf = 0; mf < 2; mf++) {
                int row = wm * 32 + mf * 16 + lr + ((g & 1) << 3);
                int ch = 2 * ks + (g >> 1);
                ldsm4(a[mf][0], a[mf][1], a[mf][2], a[mf][3],
                      abase + row * 128 + ((ch ^ (row & 7)) << 4));
            }
#pragma unroll
            for (int p = 0; p < 4; p++) {
                int row = wn * 64 + p * 16 + lr + ((g >> 1) << 3);
                int ch = 2 * ks + (g & 1);
                uint32_t b0, b1, b2, b3;
                ldsm4(b0, b1, b2, b3, wbase + row * 128 + ((ch ^ (row & 7)) << 4));
                uint32_t bA[2] = { b0, b1 }, bB[2] = { b2, b3 };
                mma16(acc[0][2 * p],     a[0], bA);
                mma16(acc[0][2 * p + 1], a[0], bB);
                mma16(acc[1][2 * p],     a[1], bA);
                mma16(acc[1][2 * p + 1], a[1], bB);
            }
        }
        __syncthreads();
    }

    // epilogue
#pragma unroll
    for (int mf = 0; mf < 2; mf++) {
        const int mb = m0 + wm * 32 + mf * 16 + (lane >> 2);
#pragma unroll
        for (int nf = 0; nf < 8; nf++) {
            const int n = n0 + wn * 64 + nf * 8 + (lane & 3) * 2;
            const float bi0 = bias[n], bi1 = bias[n + 1];
#pragma unroll
            for (int hh = 0; hh < 2; hh++) {
                const int m = mb + hh * 8;
                float v0 = acc[mf][nf][2 * hh] + bi0;
                float v1 = acc[mf][nf][2 * hh + 1] + bi1;
                if (SCALE) { v0 *= 0.125f; v1 *= 0.125f; }
                if (OUTF32) {
                    *(float2*)&Cf[(size_t)m * DD + n] = make_float2(v0, v1);
                } else {
                    __half2 hv = __floats2half2_rn(v0, v1);
                    if (LAYOUT == 0) {
                        *(__half2*)&Ch[(size_t)m * DD + n] = hv;
                    } else {
                        const int b_ = m >> 11, l_ = m & 2047;
                        const int h_ = n >> 6, hd_ = n & 63;
                        *(__half2*)&Ch[(((size_t)(b_ * HH + h_)) * LL + l_) * HD + hd_] = hv;
                    }
                }
            }
        }
    }
}

// ---------------------------------------------------------------- attention
// CTA = 128 Q rows of one (b,h); 8 warps each 16 rows; K/V tiles 64 rows,
// double-buffered via cp.async. Q pre-scaled by 0.125 in its projection.
__global__ __launch_bounds__(256, 2) void attn_h(const __half* __restrict__ q,
                                                 const __half* __restrict__ k,
                                                 const __half* __restrict__ v,
                                                 __half* __restrict__ out)
{
    extern __shared__ __half smh[];
    const uint32_t sbase = smem_u32(smh);
    const int tid = threadIdx.x, lane = tid & 31, warp = tid >> 5;
    const int qt = blockIdx.x, h = blockIdx.y, b = blockIdx.z;
    const size_t base = ((size_t)(b * HH + h)) * LL * HD;
    const __half* qg = q + base + (size_t)qt * 128 * HD;
    const int g = lane >> 3, lr = lane & 7, r = lane >> 2, c = lane & 3;

    // bytes: Q [0,16384); K(buf) at 16384+buf*16384; V(buf) at 24576+buf*16384
#pragma unroll
    for (int i = 0; i < 4; i++) {
        int lin = tid + i * 256;
        int row = lin >> 3, cc = lin & 7;
        cpasync16(sbase + row * 128 + ((cc ^ (row & 7)) << 4), qg + row * HD + cc * 8);
    }
    auto issueKV = [&](int buf, int kt) {
        const __half* kg = k + base + (size_t)kt * 64 * HD;
        const __half* vg = v + base + (size_t)kt * 64 * HD;
#pragma unroll
        for (int i = 0; i < 2; i++) {
            int lin = tid + i * 256;
            int row = lin >> 3, cc = lin & 7;
            uint32_t soff = (uint32_t)(row * 128 + ((cc ^ (row & 7)) << 4));
            cpasync16(sbase + 16384 + buf * 16384 + soff, kg + row * HD + cc * 8);
            cpasync16(sbase + 24576 + buf * 16384 + soff, vg + row * HD + cc * 8);
        }
    };
    issueKV(0, 0); cp_commit();

    uint32_t qa[4][4];
    float o[8][4];
#pragma unroll
    for (int nf = 0; nf < 8; nf++)
#pragma unroll
        for (int j = 0; j < 4; j++) o[nf][j] = 0.f;
    float mA = -1e30f, mB = -1e30f, lsA = 0.f, lsB = 0.f;

    for (int kt = 0; kt < LL / 64; kt++) {
        if (kt < LL / 64 - 1) { issueKV((kt + 1) & 1, kt + 1); cp_commit(); cp_wait1(); }
        else cp_wait0();
        __syncthreads();

        if (kt == 0) {
#pragma unroll
            for (int ks = 0; ks < 4; ks++) {
                int row = warp * 16 + lr + ((g & 1) << 3);
                int ch = 2 * ks + (g >> 1);
                ldsm4(qa[ks][0], qa[ks][1], qa[ks][2], qa[ks][3],
                      sbase + row * 128 + ((ch ^ (row & 7)) << 4));
            }
        }
        const uint32_t kb_ = sbase + 16384 + (kt & 1) * 16384;
        const uint32_t vb_ = sbase + 24576 + (kt & 1) * 16384;

        // S = Qs @ K^T  (16x64 per warp)
        float s[8][4];
#pragma unroll
        for (int nf = 0; nf < 8; nf++)
#pragma unroll
            for (int j = 0; j < 4; j++) s[nf][j] = 0.f;
#pragma unroll
        for (int ks = 0; ks < 4; ks++)
#pragma unroll
            for (int p = 0; p < 4; p++) {
                int row = p * 16 + lr + ((g >> 1) << 3);
                int ch = 2 * ks + (g & 1);
                uint32_t b0, b1, b2, b3;
                ldsm4(b0, b1, b2, b3, kb_ + row * 128 + ((ch ^ (row & 7)) << 4));
                uint32_t xA[2] = { b0, b1 }, xB[2] = { b2, b3 };
                mma16(s[2 * p],     qa[ks], xA);
                mma16(s[2 * p + 1], qa[ks], xB);
            }

        // online softmax (rows r and r+8 of this warp's 16)
        float rmA = -1e30f, rmB = -1e30f;
#pragma unroll
        for (int nf = 0; nf < 8; nf++) {
            rmA = fmaxf(rmA, fmaxf(s[nf][0], s[nf][1]));
            rmB = fmaxf(rmB, fmaxf(s[nf][2], s[nf][3]));
        }
#pragma unroll
        for (int ofs = 1; ofs < 4; ofs <<= 1) {
            rmA = fmaxf(rmA, __shfl_xor_sync(0xffffffffu, rmA, ofs));
            rmB = fmaxf(rmB, __shfl_xor_sync(0xffffffffu, rmB, ofs));
        }
        const float mnA = fmaxf(mA, rmA), mnB = fmaxf(mB, rmB);
        const float aA = __expf(mA - mnA), aB = __expf(mB - mnB);
        mA = mnA; mB = mnB;

        float smA = 0.f, smB = 0.f;
#pragma unroll
        for (int nf = 0; nf < 8; nf++) {
            s[nf][0] = __expf(s[nf][0] - mnA);
            s[nf][1] = __expf(s[nf][1] - mnA);
            s[nf][2] = __expf(s[nf][2] - mnB);
            s[nf][3] = __expf(s[nf][3] - mnB);
            smA += s[nf][0] + s[nf][1];
            smB += s[nf][2] + s[nf][3];
        }
#pragma unroll
        for (int ofs = 1; ofs < 4; ofs <<= 1) {
            smA += __shfl_xor_sync(0xffffffffu, smA, ofs);
            smB += __shfl_xor_sync(0xffffffffu, smB, ofs);
        }
        lsA = lsA * aA + smA;
        lsB = lsB * aB + smB;
#pragma unroll
        for (int nf = 0; nf < 8; nf++) {
            o[nf][0] *= aA; o[nf][1] *= aA;
            o[nf][2] *= aB; o[nf][3] *= aB;
        }

        // P in C-layout == A-layout for m16n8k16: pure register repack
        uint32_t pa[4][4];
#pragma unroll
        for (int t = 0; t < 4; t++) {
            pa[t][0] = packh2(s[2 * t][0],     s[2 * t][1]);
            pa[t][1] = packh2(s[2 * t][2],     s[2 * t][3]);
            pa[t][2] = packh2(s[2 * t + 1][0], s[2 * t + 1][1]);
            pa[t][3] = packh2(s[2 * t + 1][2], s[2 * t + 1][3]);
        }

        // O += P @ V (ldmatrix.trans for V)
#pragma unroll
        for (int t = 0; t < 4; t++)
#pragma unroll
            for (int p = 0; p < 4; p++) {
                int row = 16 * t + lr + ((g & 1) << 3);
                int ch = 2 * p + (g >> 1);
                uint32_t b0, b1, b2, b3;
                ldsm4t(b0, b1, b2, b3, vb_ + row * 128 + ((ch ^ (row & 7)) << 4));
                uint32_t xA[2] = { b0, b1 }, xB[2] = { b2, b3 };
                mma16(o[2 * p],     pa[t], xA);
                mma16(o[2 * p + 1], pa[t], xB);
            }
        __syncthreads();
    }

    const float iA = 1.f / lsA, iB = 1.f / lsB;
    const int lrow = qt * 128 + warp * 16 + r;
#pragma unroll
    for (int nf = 0; nf < 8; nf++) {
        const int d0 = h * HD + nf * 8 + 2 * c;
        *(__half2*)&out[((size_t)b * LL + lrow) * DD + d0] =
            __floats2half2_rn(o[nf][0] * iA, o[nf][1] * iA);
        *(__half2*)&out[((size_t)b * LL + lrow + 8) * DD + d0] =
            __floats2half2_rn(o[nf][2] * iB, o[nf][3] * iB);
    }
}

// ---------------------------------------------------------------- launch
extern "C" void kernel_launch(void* const* d_in, const int* in_sizes, int n_in,
                              void* d_out, int out_size) {
    const float* x  = (const float*)d_in[0];
    const float* Wq = (const float*)d_in[1];
    const float* bq = (const float*)d_in[2];
    const float* Wk = (const float*)d_in[3];
    const float* bk = (const float*)d_in[4];
    const float* Wv = (const float*)d_in[5];
    const float* bv = (const float*)d_in[6];
    const float* Wo = (const float*)d_in[7];
    const float* bo = (const float*)d_in[8];
    float* out = (float*)d_out;

    __half *xh, *wh, *qh, *kh, *vh, *ah;
    cudaGetSymbolAddress((void**)&xh, g_xh);
    cudaGetSymbolAddress((void**)&wh, g_wh);
    cudaGetSymbolAddress((void**)&qh, g_qh);
    cudaGetSymbolAddress((void**)&kh, g_kh);
    cudaGetSymbolAddress((void**)&vh, g_vh);
    cudaGetSymbolAddress((void**)&ah, g_ah);

    to_half<<<MM * DD / 4 / 256, 256>>>(x, xh, MM * DD / 4);
    to_half<<<DD * DD / 4 / 256, 256>>>(Wq, wh + 0 * DD * DD, DD * DD / 4);
    to_half<<<DD * DD / 4 / 256, 256>>>(Wk, wh + 1 * DD * DD, DD * DD / 4);
    to_half<<<DD * DD / 4 / 256, 256>>>(Wv, wh + 2 * DD * DD, DD * DD / 4);
    to_half<<<DD * DD / 4 / 256, 256>>>(Wo, wh + 3 * DD * DD, DD * DD / 4);

    const int gsm = 65536;
    cudaFuncSetAttribute(gemm_h<1, 1, 0>, cudaFuncAttributeMaxDynamicSharedMemorySize, gsm);
    cudaFuncSetAttribute(gemm_h<1, 0, 0>, cudaFuncAttributeMaxDynamicSharedMemorySize, gsm);
    cudaFuncSetAttribute(gemm_h<0, 0, 1>, cudaFuncAttributeMaxDynamicSharedMemorySize, gsm);

    dim3 gg(DD / 128, MM / 128);
    gemm_h<1, 1, 0><<<gg, 256, gsm>>>(xh, wh + 0 * DD * DD, bq, nullptr, qh);
    gemm_h<1, 0, 0><<<gg, 256, gsm>>>(xh, wh + 1 * DD * DD, bk, nullptr, kh);
    gemm_h<1, 0, 0><<<gg, 256, gsm>>>(xh, wh + 2 * DD * DD, bv, nullptr, vh);

    const int asm_ = 49152;
    cudaFuncSetAttribute(attn_h, cudaFuncAttributeMaxDynamicSharedMemorySize, asm_);
    attn_h<<<dim3(LL / 128, HH, BB), 256, asm_>>>(qh, kh, vh, ah);

    gemm_h<0, 0, 1><<<gg, 256, gsm>>>(ah, wh + 3 * DD * DD, bo, out, nullptr);
}

// round 5
// speedup vs baseline: 10.0083x; 1.1279x over previous
#include <cuda_runtime.h>
#include <cuda_fp16.h>
#include <stdint.h>

#define BB 2
#define LL 2048
#define DD 1024
#define HH 16
#define HD 64
#define MM (BB*LL)   // 4096

__device__ __align__(128) __half g_xh[MM * DD];
__device__ __align__(128) __half g_wh[4][DD * DD];
__device__ __align__(128) __half g_qh[BB * LL * DD];
__device__ __align__(128) __half g_kh[BB * LL * DD];
__device__ __align__(128) __half g_vh[BB * LL * DD];
__device__ __align__(128) __half g_ah[BB * LL * DD];

// ---------------------------------------------------------------- helpers
__device__ __forceinline__ uint32_t smem_u32(const void* p) {
    return (uint32_t)__cvta_generic_to_shared(p);
}
__device__ __forceinline__ void cpasync16(uint32_t s, const void* g) {
    asm volatile("cp.async.cg.shared.global [%0], [%1], 16;\n" :: "r"(s), "l"(g));
}
__device__ __forceinline__ void cp_commit() { asm volatile("cp.async.commit_group;\n"); }
__device__ __forceinline__ void cp_wait0() { asm volatile("cp.async.wait_group 0;\n"); }
__device__ __forceinline__ void cp_wait1() { asm volatile("cp.async.wait_group 1;\n"); }

__device__ __forceinline__ void ldsm4(uint32_t& r0, uint32_t& r1, uint32_t& r2, uint32_t& r3, uint32_t a) {
    asm volatile("ldmatrix.sync.aligned.m8n8.x4.shared.b16 {%0,%1,%2,%3}, [%4];\n"
                 : "=r"(r0), "=r"(r1), "=r"(r2), "=r"(r3) : "r"(a));
}
__device__ __forceinline__ void ldsm4t(uint32_t& r0, uint32_t& r1, uint32_t& r2, uint32_t& r3, uint32_t a) {
    asm volatile("ldmatrix.sync.aligned.m8n8.x4.trans.shared.b16 {%0,%1,%2,%3}, [%4];\n"
                 : "=r"(r0), "=r"(r1), "=r"(r2), "=r"(r3) : "r"(a));
}
__device__ __forceinline__ void mma16(float* d, const uint32_t* a, const uint32_t* b) {
    asm volatile("mma.sync.aligned.m16n8k16.row.col.f32.f16.f16.f32 "
                 "{%0,%1,%2,%3}, {%4,%5,%6,%7}, {%8,%9}, {%0,%1,%2,%3};"
                 : "+f"(d[0]), "+f"(d[1]), "+f"(d[2]), "+f"(d[3])
                 : "r"(a[0]), "r"(a[1]), "r"(a[2]), "r"(a[3]), "r"(b[0]), "r"(b[1]));
}
__device__ __forceinline__ uint32_t packh2(float a, float b) {
    __half2 t = __floats2half2_rn(a, b);
    return *reinterpret_cast<uint32_t*>(&t);
}
__device__ __forceinline__ float ex2(float x) {
    float r; asm("ex2.approx.ftz.f32 %0, %1;" : "=f"(r) : "f"(x)); return r;
}

// ---------------------------------------------------------------- convert (x + 4 weights)
__global__ void cvt_all(const float* __restrict__ x,
                        const float* __restrict__ wq, const float* __restrict__ wk,
                        const float* __restrict__ wv, const float* __restrict__ wo,
                        __half* __restrict__ xh, __half* __restrict__ wh) {
    int i = blockIdx.x * blockDim.x + threadIdx.x;
    const float* src; __half* dst; int off;
    if (i < (MM * DD / 4)) { src = x; dst = xh; off = i; }
    else {
        int j = i - MM * DD / 4;
        int r = j >> 18;
        int o = j & 262143;
        src = (r == 0) ? wq : (r == 1) ? wk : (r == 2) ? wv : wo;
        dst = wh + (size_t)r * DD * DD;
        off = o;
    }
    float4 v = ((const float4*)src)[off];
    __half2* o2 = (__half2*)dst + (size_t)off * 2;
    o2[0] = __floats2half2_rn(v.x, v.y);
    o2[1] = __floats2half2_rn(v.z, v.w);
}

// Q pre-scale: 1/sqrt(64) * log2(e), so softmax can use raw ex2.
#define QSCALE (0.125f * 1.44269504088896f)

// ---------------------------------------------------------------- fused QKV GEMM
// A:(4096,1024) fp16, W: concatenated [Wq;Wk;Wv] (3072,1024) fp16.
// CTA tile 128x128x64, 8 warps (4m x 2n). Output (B,H,L,HD) fp16;
// the q block (n0 < 1024) gets QSCALE folded in.
__global__ __launch_bounds__(256, 2) void gemm_qkv(const __half* __restrict__ A,
                                                   const __half* __restrict__ W,
                                                   const float* __restrict__ bq,
                                                   const float* __restrict__ bk,
                                                   const float* __restrict__ bv,
                                                   __half* __restrict__ qo,
                                                   __half* __restrict__ ko,
                                                   __half* __restrict__ vo)
{
    extern __shared__ __half smh[];
    const uint32_t sbase = smem_u32(smh);
    const int tid = threadIdx.x, lane = tid & 31, warp = tid >> 5;
    const int wm = warp & 3, wn = warp >> 2;
    const int m0 = blockIdx.y * 128, n0 = blockIdx.x * 128;
    const int g = lane >> 3, lr = lane & 7;

    const int which = n0 >> 10;                     // 0=q, 1=k, 2=v (uniform per CTA)
    const float* bias = (which == 0) ? bq : (which == 1) ? bk : bv;
    __half* outp = (which == 0) ? qo : (which == 1) ? ko : vo;
    const float sc = (which == 0) ? QSCALE : 1.f;

    float acc[2][8][4];
#pragma unroll
    for (int mf = 0; mf < 2; mf++)
#pragma unroll
        for (int nf = 0; nf < 8; nf++)
#pragma unroll
            for (int j = 0; j < 4; j++) acc[mf][nf][j] = 0.f;

    auto issue = [&](int buf, int k0) {
#pragma unroll
        for (int i = 0; i < 4; i++) {
            int lin = tid + i * 256;
            int row = lin >> 3, cc = lin & 7;
            uint32_t soff = (uint32_t)(row * 128 + ((cc ^ (row & 7)) << 4));
            cpasync16(sbase + buf * 16384 + soff, A + (size_t)(m0 + row) * DD + k0 + cc * 8);
            cpasync16(sbase + 32768 + buf * 16384 + soff, W + (size_t)(n0 + row) * DD + k0 + cc * 8);
        }
    };

    issue(0, 0); cp_commit();

    for (int kt = 0; kt < 16; kt++) {
        if (kt < 15) { issue((kt + 1) & 1, (kt + 1) * 64); cp_commit(); cp_wait1(); }
        else cp_wait0();
        __syncthreads();

        const uint32_t abase = sbase + (kt & 1) * 16384;
        const uint32_t wbase = sbase + 32768 + (kt & 1) * 16384;
#pragma unroll
        for (int ks = 0; ks < 4; ks++) {
            uint32_t a[2][4];
#pragma unroll
            for (int mf = 0; mf < 2; mf++) {
                int row = wm * 32 + mf * 16 + lr + ((g & 1) << 3);
                int ch = 2 * ks + (g >> 1);
                ldsm4(a[mf][0], a[mf][1], a[mf][2], a[mf][3],
                      abase + row * 128 + ((ch ^ (row & 7)) << 4));
            }
#pragma unroll
            for (int p = 0; p < 4; p++) {
                int row = wn * 64 + p * 16 + lr + ((g >> 1) << 3);
                int ch = 2 * ks + (g & 1);
                uint32_t b0, b1, b2, b3;
                ldsm4(b0, b1, b2, b3, wbase + row * 128 + ((ch ^ (row & 7)) << 4));
                uint32_t bA[2] = { b0, b1 }, bB[2] = { b2, b3 };
                mma16(acc[0][2 * p],     a[0], bA);
                mma16(acc[0][2 * p + 1], a[0], bB);
                mma16(acc[1][2 * p],     a[1], bA);
                mma16(acc[1][2 * p + 1], a[1], bB);
            }
        }
        __syncthreads();
    }

#pragma unroll
    for (int mf = 0; mf < 2; mf++) {
        const int mb = m0 + wm * 32 + mf * 16 + (lane >> 2);
#pragma unroll
        for (int nf = 0; nf < 8; nf++) {
            const int nloc = (n0 & 1023) + wn * 64 + nf * 8 + (lane & 3) * 2;
            const float bi0 = bias[nloc], bi1 = bias[nloc + 1];
            const int h_ = nloc >> 6, hd_ = nloc & 63;
#pragma unroll
            for (int hh = 0; hh < 2; hh++) {
                const int m = mb + hh * 8;
                float v0 = (acc[mf][nf][2 * hh]     + bi0) * sc;
                float v1 = (acc[mf][nf][2 * hh + 1] + bi1) * sc;
                const int b_ = m >> 11, l_ = m & 2047;
                *(__half2*)&outp[(((size_t)(b_ * HH + h_)) * LL + l_) * HD + hd_] =
                    __floats2half2_rn(v0, v1);
            }
        }
    }
}

// ---------------------------------------------------------------- output GEMM (fp32 out)
__global__ __launch_bounds__(256, 2) void gemm_o(const __half* __restrict__ A,
                                                 const __half* __restrict__ W,
                                                 const float* __restrict__ bias,
                                                 float* __restrict__ Cf)
{
    extern __shared__ __half smh[];
    const uint32_t sbase = smem_u32(smh);
    const int tid = threadIdx.x, lane = tid & 31, warp = tid >> 5;
    const int wm = warp & 3, wn = warp >> 2;
    const int m0 = blockIdx.y * 128, n0 = blockIdx.x * 128;
    const int g = lane >> 3, lr = lane & 7;

    float acc[2][8][4];
#pragma unroll
    for (int mf = 0; mf < 2; mf++)
#pragma unroll
        for (int nf = 0; nf < 8; nf++)
#pragma unroll
            for (int j = 0; j < 4; j++) acc[mf][nf][j] = 0.f;

    auto issue = [&](int buf, int k0) {
#pragma unroll
        for (int i = 0; i < 4; i++) {
            int lin = tid + i * 256;
            int row = lin >> 3, cc = lin & 7;
            uint32_t soff = (uint32_t)(row * 128 + ((cc ^ (row & 7)) << 4));
            cpasync16(sbase + buf * 16384 + soff, A + (size_t)(m0 + row) * DD + k0 + cc * 8);
            cpasync16(sbase + 32768 + buf * 16384 + soff, W + (size_t)(n0 + row) * DD + k0 + cc * 8);
        }
    };

    issue(0, 0); cp_commit();

    for (int kt = 0; kt < 16; kt++) {
        if (kt < 15) { issue((kt + 1) & 1, (kt + 1) * 64); cp_commit(); cp_wait1(); }
        else cp_wait0();
        __syncthreads();

        const uint32_t abase = sbase + (kt & 1) * 16384;
        const uint32_t wbase = sbase + 32768 + (kt & 1) * 16384;
#pragma unroll
        for (int ks = 0; ks < 4; ks++) {
            uint32_t a[2][4];
#pragma unroll
            for (int mf = 0; mf < 2; mf++) {
                int row = wm * 32 + mf * 16 + lr + ((g & 1) << 3);
                int ch = 2 * ks + (g >> 1);
                ldsm4(a[mf][0], a[mf][1], a[mf][2], a[mf][3],
                      abase + row * 128 + ((ch ^ (row & 7)) << 4));
            }
#pragma unroll
            for (int p = 0; p < 4; p++) {
                int row = wn * 64 + p * 16 + lr + ((g >> 1) << 3);
                int ch = 2 * ks + (g & 1);
                uint32_t b0, b1, b2, b3;
                ldsm4(b0, b1, b2, b3, wbase + row * 128 + ((ch ^ (row & 7)) << 4));
                uint32_t bA[2] = { b0, b1 }, bB[2] = { b2, b3 };
                mma16(acc[0][2 * p],     a[0], bA);
                mma16(acc[0][2 * p + 1], a[0], bB);
                mma16(acc[1][2 * p],     a[1], bA);
                mma16(acc[1][2 * p + 1], a[1], bB);
            }
        }
        __syncthreads();
    }

#pragma unroll
    for (int mf = 0; mf < 2; mf++) {
        const int mb = m0 + wm * 32 + mf * 16 + (lane >> 2);
#pragma unroll
        for (int nf = 0; nf < 8; nf++) {
            const int n = n0 + wn * 64 + nf * 8 + (lane & 3) * 2;
            const float bi0 = bias[n], bi1 = bias[n + 1];
#pragma unroll
            for (int hh = 0; hh < 2; hh++) {
                const int m = mb + hh * 8;
                *(float2*)&Cf[(size_t)m * DD + n] =
                    make_float2(acc[mf][nf][2 * hh] + bi0, acc[mf][nf][2 * hh + 1] + bi1);
            }
        }
    }
}

// ---------------------------------------------------------------- attention
// CTA = 128 Q rows of one (b,h); 8 warps x 16 rows. 3-stage KV ring via
// cp.async -> exactly one __syncthreads per 64-row KV tile. Softmax in exp2
// domain (Q pre-scaled by 0.125*log2e).
// smem bytes: Q [0,16384); stage s: K at 16384+s*16384, V at 24576+s*16384.
#define ATT_SMEM 65536

__global__ __launch_bounds__(256, 2) void attn_h(const __half* __restrict__ q,
                                                 const __half* __restrict__ k,
                                                 const __half* __restrict__ v,
                                                 __half* __restrict__ out)
{
    extern __shared__ __half smh[];
    const uint32_t sbase = smem_u32(smh);
    const int tid = threadIdx.x, lane = tid & 31, warp = tid >> 5;
    const int qt = blockIdx.x, h = blockIdx.y, b = blockIdx.z;
    const size_t base = ((size_t)(b * HH + h)) * LL * HD;
    const __half* qg = q + base + (size_t)qt * 128 * HD;
    const int g = lane >> 3, lr = lane & 7, r = lane >> 2, c = lane & 3;

#pragma unroll
    for (int i = 0; i < 4; i++) {
        int lin = tid + i * 256;
        int row = lin >> 3, cc = lin & 7;
        cpasync16(sbase + row * 128 + ((cc ^ (row & 7)) << 4), qg + row * HD + cc * 8);
    }
    cp_commit();

    auto issueKV = [&](int st, int kt) {
        const __half* kg = k + base + (size_t)kt * 64 * HD;
        const __half* vg = v + base + (size_t)kt * 64 * HD;
#pragma unroll
        for (int i = 0; i < 2; i++) {
            int lin = tid + i * 256;
            int row = lin >> 3, cc = lin & 7;
            uint32_t soff = (uint32_t)(row * 128 + ((cc ^ (row & 7)) << 4));
            cpasync16(sbase + 16384 + st * 16384 + soff, kg + row * HD + cc * 8);
            cpasync16(sbase + 24576 + st * 16384 + soff, vg + row * HD + cc * 8);
        }
        cp_commit();
    };
    issueKV(0, 0);
    issueKV(1, 1);

    uint32_t qa[4][4];
    float o[8][4];
#pragma unroll
    for (int nf = 0; nf < 8; nf++)
#pragma unroll
        for (int j = 0; j < 4; j++) o[nf][j] = 0.f;
    float mA = -1e30f, mB = -1e30f, lsA = 0.f, lsB = 0.f;

    const int NT = LL / 64;   // 32
    int st = 0;
    for (int kt = 0; kt < NT; kt++) {
        if (kt < NT - 1) cp_wait1(); else cp_wait0();
        __syncthreads();
        if (kt + 2 < NT) issueKV((st + 2) % 3, kt + 2);

        if (kt == 0) {
#pragma unroll
            for (int ks = 0; ks < 4; ks++) {
                int row = warp * 16 + lr + ((g & 1) << 3);
                int ch = 2 * ks + (g >> 1);
                ldsm4(qa[ks][0], qa[ks][1], qa[ks][2], qa[ks][3],
                      sbase + row * 128 + ((ch ^ (row & 7)) << 4));
            }
        }
        const uint32_t kb_ = sbase + 16384 + st * 16384;
        const uint32_t vb_ = sbase + 24576 + st * 16384;

        float s[8][4];
#pragma unroll
        for (int nf = 0; nf < 8; nf++)
#pragma unroll
            for (int j = 0; j < 4; j++) s[nf][j] = 0.f;
#pragma unroll
        for (int ks = 0; ks < 4; ks++)
#pragma unroll
            for (int p = 0; p < 4; p++) {
                int row = p * 16 + lr + ((g >> 1) << 3);
                int ch = 2 * ks + (g & 1);
                uint32_t b0, b1, b2, b3;
                ldsm4(b0, b1, b2, b3, kb_ + row * 128 + ((ch ^ (row & 7)) << 4));
                uint32_t xA[2] = { b0, b1 }, xB[2] = { b2, b3 };
                mma16(s[2 * p],     qa[ks], xA);
                mma16(s[2 * p + 1], qa[ks], xB);
            }

        float rmA = -1e30f, rmB = -1e30f;
#pragma unroll
        for (int nf = 0; nf < 8; nf++) {
            rmA = fmaxf(rmA, fmaxf(s[nf][0], s[nf][1]));
            rmB = fmaxf(rmB, fmaxf(s[nf][2], s[nf][3]));
        }
#pragma unroll
        for (int ofs = 1; ofs < 4; ofs <<= 1) {
            rmA = fmaxf(rmA, __shfl_xor_sync(0xffffffffu, rmA, ofs));
            rmB = fmaxf(rmB, __shfl_xor_sync(0xffffffffu, rmB, ofs));
        }
        const float mnA = fmaxf(mA, rmA), mnB = fmaxf(mB, rmB);
        const float aA = ex2(mA - mnA), aB = ex2(mB - mnB);
        mA = mnA; mB = mnB;

        float smA = 0.f, smB = 0.f;
#pragma unroll
        for (int nf = 0; nf < 8; nf++) {
            s[nf][0] = ex2(s[nf][0] - mnA);
            s[nf][1] = ex2(s[nf][1] - mnA);
            s[nf][2] = ex2(s[nf][2] - mnB);
            s[nf][3] = ex2(s[nf][3] - mnB);
            smA += s[nf][0] + s[nf][1];
            smB += s[nf][2] + s[nf][3];
        }
#pragma unroll
        for (int ofs = 1; ofs < 4; ofs <<= 1) {
            smA += __shfl_xor_sync(0xffffffffu, smA, ofs);
            smB += __shfl_xor_sync(0xffffffffu, smB, ofs);
        }
        lsA = lsA * aA + smA;
        lsB = lsB * aB + smB;
#pragma unroll
        for (int nf = 0; nf < 8; nf++) {
            o[nf][0] *= aA; o[nf][1] *= aA;
            o[nf][2] *= aB; o[nf][3] *= aB;
        }

        uint32_t pa[4][4];
#pragma unroll
        for (int t = 0; t < 4; t++) {
            pa[t][0] = packh2(s[2 * t][0],     s[2 * t][1]);
            pa[t][1] = packh2(s[2 * t][2],     s[2 * t][3]);
            pa[t][2] = packh2(s[2 * t + 1][0], s[2 * t + 1][1]);
            pa[t][3] = packh2(s[2 * t + 1][2], s[2 * t + 1][3]);
        }

#pragma unroll
        for (int t = 0; t < 4; t++)
#pragma unroll
            for (int p = 0; p < 4; p++) {
                int row = 16 * t + lr + ((g & 1) << 3);
                int ch = 2 * p + (g >> 1);
                uint32_t b0, b1, b2, b3;
                ldsm4t(b0, b1, b2, b3, vb_ + row * 128 + ((ch ^ (row & 7)) << 4));
                uint32_t xA[2] = { b0, b1 }, xB[2] = { b2, b3 };
                mma16(o[2 * p],     pa[t], xA);
                mma16(o[2 * p + 1], pa[t], xB);
            }
        st = (st + 1) % 3;
    }

    const float iA = 1.f / lsA, iB = 1.f / lsB;
    const int lrow = qt * 128 + warp * 16 + r;
#pragma unroll
    for (int nf = 0; nf < 8; nf++) {
        const int d0 = h * HD + nf * 8 + 2 * c;
        *(__half2*)&out[((size_t)b * LL + lrow) * DD + d0] =
            __floats2half2_rn(o[nf][0] * iA, o[nf][1] * iA);
        *(__half2*)&out[((size_t)b * LL + lrow + 8) * DD + d0] =
            __floats2half2_rn(o[nf][2] * iB, o[nf][3] * iB);
    }
}

// ---------------------------------------------------------------- launch
extern "C" void kernel_launch(void* const* d_in, const int* in_sizes, int n_in,
                              void* d_out, int out_size) {
    const float* x  = (const float*)d_in[0];
    const float* Wq = (const float*)d_in[1];
    const float* bq = (const float*)d_in[2];
    const float* Wk = (const float*)d_in[3];
    const float* bk = (const float*)d_in[4];
    const float* Wv = (const float*)d_in[5];
    const float* bv = (const float*)d_in[6];
    const float* Wo = (const float*)d_in[7];
    const float* bo = (const float*)d_in[8];
    float* out = (float*)d_out;

    __half *xh, *wh, *qh, *kh, *vh, *ah;
    cudaGetSymbolAddress((void**)&xh, g_xh);
    cudaGetSymbolAddress((void**)&wh, g_wh);
    cudaGetSymbolAddress((void**)&qh, g_qh);
    cudaGetSymbolAddress((void**)&kh, g_kh);
    cudaGetSymbolAddress((void**)&vh, g_vh);
    cudaGetSymbolAddress((void**)&ah, g_ah);

    cvt_all<<<(MM * DD / 4 + 4 * DD * DD / 4) / 256, 256>>>(x, Wq, Wk, Wv, Wo, xh, wh);

    const int gsm = 65536;
    cudaFuncSetAttribute(gemm_qkv, cudaFuncAttributeMaxDynamicSharedMemorySize, gsm);
    cudaFuncSetAttribute(gemm_o,   cudaFuncAttributeMaxDynamicSharedMemorySize, gsm);
    cudaFuncSetAttribute(attn_h,   cudaFuncAttributeMaxDynamicSharedMemorySize, ATT_SMEM);

    gemm_qkv<<<dim3(3 * DD / 128, MM / 128), 256, gsm>>>(xh, wh, bq, bk, bv, qh, kh, vh);
    attn_h<<<dim3(LL / 128, HH, BB), 256, ATT_SMEM>>>(qh, kh, vh, ah);
    gemm_o<<<dim3(DD / 128, MM / 128), 256, gsm>>>(ah, wh + 3 * DD * DD, bo, out);
}